// round 1
// baseline (speedup 1.0000x reference)
#include <cuda_runtime.h>
#include <cstdint>

// Batched 8-qubit circuit expectation, fully closed-form.
//
// Derivation summary (see analysis): the CNOT ring is GF(2)-linear with
// inv[128]=0xC0 and top-half set V = {k : parity(k & 0x7F) == 0}. The product
// state's quadratic sums factor per qubit:
//   c1 = rsqrt(1+x^2), c2 = rsqrt(1+x^4)
//   |a0|^2+|a1|^2 = 1,  |a0|^2-|a1|^2 = c1
//   2Re(a0*conj(a1)) =  x*c1*c2
//   2Im(a0*conj(a1)) = -x^3*c1*c2
// and rymat(2)@rymat(1)@rymat(0) is a rotation by (sum w)/2, giving
//   out = 0.5*cosh(Si) + 0.5*cos(Sr)*Q - 0.5*sin(Sr)*W - 0.5*sinh(Si)*Xim
// with Sr = sum(w_re), Si = sum(w_im),
//   Q   = prod_{q=1..7} c1_q
//   W   = (x0 c1_0 c2_0) * (x1 c1_1 c2_1)
//   Xim = -(x0 c1_0 c2_0) * (x1^3 c1_1 c2_1) * prod_{q=2..7} c1_q

__global__ __launch_bounds__(256)
void qc_expect_kernel(const float* __restrict__ x,
                      const float* __restrict__ wre,
                      const float* __restrict__ wim,
                      float* __restrict__ out,
                      int batch)
{
    int b = blockIdx.x * blockDim.x + threadIdx.x;
    if (b >= batch) return;

    // --- rotation scalars (uniform across threads; broadcast loads) ---
    float Sr = wre[0] + wre[1] + wre[2];
    float Si = wim[0] + wim[1] + wim[2];
    float e  = expf(Si);
    float ei = 1.0f / e;
    float K0 = 0.25f * (e + ei);   // 0.5*cosh(Si)
    float K3 = -0.25f * (e - ei);  // -0.5*sinh(Si)
    float sA, cA;
    sincosf(Sr, &sA, &cA);
    float K1 = 0.5f * cA;          // 0.5*cos(Sr)
    float K2 = -0.5f * sA;         // -0.5*sin(Sr)

    // --- load 8 inputs (2x float4, 32B/thread, contiguous per warp) ---
    const float4* xp = reinterpret_cast<const float4*>(x + (size_t)b * 8);
    float4 v0 = xp[0];
    float4 v1 = xp[1];
    float xs[8] = {v0.x, v0.y, v0.z, v0.w, v1.x, v1.y, v1.z, v1.w};

    float c1[8];
#pragma unroll
    for (int q = 0; q < 8; ++q) {
        float xx = xs[q] * xs[q];
        c1[q] = rsqrtf(fmaf(xs[q], xs[q], 1.0f));
        (void)xx;
    }

    // c2 only needed for qubits 0 and 1
    float x0 = xs[0], x1 = xs[1];
    float x0s = x0 * x0, x1s = x1 * x1;
    float c2_0 = rsqrtf(fmaf(x0s, x0s, 1.0f));
    float c2_1 = rsqrtf(fmaf(x1s, x1s, 1.0f));

    float prod27 = c1[2] * c1[3] * c1[4] * c1[5] * c1[6] * c1[7];
    float Q = c1[1] * prod27;

    float tR0 = x0 * c1[0] * c2_0;
    float tR1 = x1 * c1[1] * c2_1;

    float W   = tR0 * tR1;
    float Xim = -tR0 * (x1s * tR1) * prod27;

    out[b] = fmaf(K1, Q, fmaf(K2, W, fmaf(K3, Xim, K0)));
}

extern "C" void kernel_launch(void* const* d_in, const int* in_sizes, int n_in,
                              void* d_out, int out_size)
{
    const float* x   = (const float*)d_in[0];
    const float* wre = (const float*)d_in[1];
    const float* wim = (const float*)d_in[2];
    float* out = (float*)d_out;

    int batch = in_sizes[0] / 8;
    int threads = 256;
    int blocks = (batch + threads - 1) / threads;
    qc_expect_kernel<<<blocks, threads>>>(x, wre, wim, out, batch);
}

// round 2
// speedup vs baseline: 1.1406x; 1.1406x over previous
#include <cuda_runtime.h>
#include <cstdint>

// Batched 8-qubit circuit expectation, fully closed-form.
//
// Math (verified R1, rel_err 2.5e-7):
//   c1 = rsqrt(1+x^2), c2 = rsqrt(1+x^4)
//   Sr = sum(w_re), Si = sum(w_im)
//   out = 0.5*cosh(Si) + 0.5*cos(Sr)*Q - 0.5*sin(Sr)*W - 0.5*sinh(Si)*Xim
//   Q   = prod_{q=1..7} c1_q
//   W   = (x0 c1_0 c2_0) * (x1 c1_1 c2_1)
//   Xim = -(x0 c1_0 c2_0) * (x1^3 c1_1 c2_1) * prod_{q=2..7} c1_q
//
// R2 change: the per-thread uniform prologue used precise-path sincosf/expf/
// fdiv (~350 redundant instructions/thread -> issue-bound at 420 instr/warp).
// Replaced with MUFU intrinsics (__sinf/__cosf/__expf); loads issued first.

__global__ __launch_bounds__(128)
void qc_expect_kernel(const float* __restrict__ x,
                      const float* __restrict__ wre,
                      const float* __restrict__ wim,
                      float* __restrict__ out,
                      int batch)
{
    int b = blockIdx.x * blockDim.x + threadIdx.x;
    if (b >= batch) return;

    // --- front-load the 32B of per-row input (2x LDG.128, coalesced) ---
    const float4* xp = reinterpret_cast<const float4*>(x + (size_t)b * 8);
    float4 v0 = xp[0];
    float4 v1 = xp[1];

    // --- rotation scalars via MUFU intrinsics (uniform; ~12 instrs) ---
    float Sr = __ldg(wre + 0) + __ldg(wre + 1) + __ldg(wre + 2);
    float Si = __ldg(wim + 0) + __ldg(wim + 1) + __ldg(wim + 2);
    float e  = __expf(Si);
    float ei = __expf(-Si);
    float K0 = 0.25f * (e + ei);    // 0.5*cosh(Si)
    float K3 = -0.25f * (e - ei);   // -0.5*sinh(Si)
    float K1 = 0.5f * __cosf(Sr);   // 0.5*cos(Sr)
    float K2 = -0.5f * __sinf(Sr);  // -0.5*sin(Sr)

    float xs[8] = {v0.x, v0.y, v0.z, v0.w, v1.x, v1.y, v1.z, v1.w};

    float c1[8];
#pragma unroll
    for (int q = 0; q < 8; ++q)
        c1[q] = rsqrtf(fmaf(xs[q], xs[q], 1.0f));

    // c2 only needed for qubits 0 and 1
    float x0 = xs[0], x1 = xs[1];
    float x0s = x0 * x0, x1s = x1 * x1;
    float c2_0 = rsqrtf(fmaf(x0s, x0s, 1.0f));
    float c2_1 = rsqrtf(fmaf(x1s, x1s, 1.0f));

    float prod27 = (c1[2] * c1[3]) * (c1[4] * c1[5]) * (c1[6] * c1[7]);
    float Q = c1[1] * prod27;

    float tR0 = x0 * c1[0] * c2_0;
    float tR1 = x1 * c1[1] * c2_1;

    float W   = tR0 * tR1;
    float Xim = -tR0 * (x1s * tR1) * prod27;

    out[b] = fmaf(K1, Q, fmaf(K2, W, fmaf(K3, Xim, K0)));
}

extern "C" void kernel_launch(void* const* d_in, const int* in_sizes, int n_in,
                              void* d_out, int out_size)
{
    const float* x   = (const float*)d_in[0];
    const float* wre = (const float*)d_in[1];
    const float* wim = (const float*)d_in[2];
    float* out = (float*)d_out;

    int batch = in_sizes[0] / 8;
    int threads = 128;
    int blocks = (batch + threads - 1) / threads;
    qc_expect_kernel<<<blocks, threads>>>(x, wre, wim, out, batch);
}